// round 5
// baseline (speedup 1.0000x reference)
#include <cuda_runtime.h>
#include <math.h>

#define NN 50000
#define EE 800000
#define HH 128
#define NC 40

// ---------------- scratch (device globals; referenced directly from device code) ----------------
__device__ int   g_is64;
__device__ int   g_cnt[NN];
__device__ int   g_rowptr[NN + 1];
__device__ int   g_wr[NN];
__device__ int   g_col[EE];
__device__ float g_dis[NN];
__device__ float g_ls[NN], g_ld[NN];
__device__ float g_h0[NN * HH];
__device__ float g_x1[NN * HH], g_x2[NN * HH], g_x3[NN * HH];
__device__ float g_hgcn[NN * HH], g_hgat[NN * HH];
__device__ float g_aggn[NN * HH], g_ginin[NN * HH], g_gcnout[NN * HH], g_gatout[NN * HH];
__device__ float g_sage[NN * HH], g_gin[NN * HH];
__device__ float g_x5[NN * HH];
__device__ float g_naw[12], g_scw[4], g_law[3];

// compile-time buffer selector (device side; avoids host symbol lookups)
template <int ID>
__device__ __forceinline__ float* buf() {
    if (ID == 0)  return g_h0;
    if (ID == 1)  return g_x1;
    if (ID == 2)  return g_x2;
    if (ID == 3)  return g_x3;
    if (ID == 4)  return g_hgcn;
    if (ID == 5)  return g_hgat;
    if (ID == 6)  return g_aggn;
    if (ID == 7)  return g_ginin;
    if (ID == 8)  return g_gcnout;
    if (ID == 9)  return g_gatout;
    if (ID == 10) return g_sage;
    if (ID == 11) return g_gin;
    return g_x5;
}

__device__ __forceinline__ float eluf(float x) { return x > 0.f ? x : expm1f(x); }

// dtype-agnostic edge accessor: idx in [0, 2*EE)
__device__ __forceinline__ int edge_at(const void* p, int idx) {
    if (g_is64) return (int)((const long long*)p)[idx];
    return ((const int*)p)[idx];
}

// ---------------- edge dtype detection ----------------
// If the buffer is int64 (little-endian, values < 2^31), every odd int32 slot
// is a zero high-word. If int32, odd slots are random node ids (not all zero).
__global__ void detect_kernel(const int* __restrict__ p) {
    __shared__ int nz;
    if (threadIdx.x == 0) nz = 0;
    __syncthreads();
    int local = 0;
    for (int i = threadIdx.x * 2 + 1; i < 8192; i += 2 * blockDim.x)
        if (p[i] != 0) local = 1;
    if (local) atomicOr(&nz, 1);
    __syncthreads();
    if (threadIdx.x == 0) g_is64 = nz ? 0 : 1;
}

// ---------------- tiny softmaxes ----------------
__global__ void softmax_small_kernel(const float* __restrict__ na,
                                     const float* __restrict__ sc,
                                     const float* __restrict__ la) {
    if (threadIdx.x != 0 || blockIdx.x != 0) return;
    for (int r = 0; r < 3; r++) {
        float m = -1e30f;
        for (int j = 0; j < 4; j++) m = fmaxf(m, na[r * 4 + j]);
        float z = 0.f;
        float e[4];
        for (int j = 0; j < 4; j++) { e[j] = expf(na[r * 4 + j] - m); z += e[j]; }
        for (int j = 0; j < 4; j++) g_naw[r * 4 + j] = e[j] / z;
    }
    for (int r = 0; r < 2; r++) {
        float m = fmaxf(sc[r * 2 + 0], sc[r * 2 + 1]);
        float e0 = expf(sc[r * 2 + 0] - m), e1 = expf(sc[r * 2 + 1] - m);
        float z = e0 + e1;
        g_scw[r * 2 + 0] = e0 / z;
        g_scw[r * 2 + 1] = e1 / z;
    }
    {
        float m = fmaxf(fmaxf(la[0], la[1]), la[2]);
        float e0 = expf(la[0] - m), e1 = expf(la[1] - m), e2 = expf(la[2] - m);
        float z = e0 + e1 + e2;
        g_law[0] = e0 / z; g_law[1] = e1 / z; g_law[2] = e2 / z;
    }
}

// ---------------- CSR build ----------------
__global__ void zero_cnt_kernel() {
    int i = blockIdx.x * blockDim.x + threadIdx.x;
    if (i < NN) g_cnt[i] = 0;
}

__global__ void count_kernel(const void* __restrict__ ei) {
    int e = blockIdx.x * blockDim.x + threadIdx.x;
    if (e >= EE) return;
    int dst = edge_at(ei, EE + e);
    if ((unsigned)dst >= NN) return;     // safety: never trap
    atomicAdd(&g_cnt[dst], 1);
}

__global__ void scan_kernel() {
    __shared__ int sh[1024];
    __shared__ int carry_s;
    int tid = threadIdx.x;
    if (tid == 0) carry_s = 0;
    __syncthreads();
    for (int base = 0; base < NN; base += 1024) {
        int v = (base + tid < NN) ? g_cnt[base + tid] : 0;
        sh[tid] = v;
        __syncthreads();
        for (int off = 1; off < 1024; off <<= 1) {
            int t = (tid >= off) ? sh[tid - off] : 0;
            __syncthreads();
            sh[tid] += t;
            __syncthreads();
        }
        int excl = carry_s + sh[tid] - v;
        if (base + tid < NN) { g_rowptr[base + tid] = excl; g_wr[base + tid] = excl; }
        int total = sh[1023];
        __syncthreads();
        if (tid == 0) carry_s += total;
        __syncthreads();
    }
    if (tid == 0) g_rowptr[NN] = carry_s;
}

__global__ void fill_kernel(const void* __restrict__ ei) {
    int e = blockIdx.x * blockDim.x + threadIdx.x;
    if (e >= EE) return;
    int src = edge_at(ei, e);
    int dst = edge_at(ei, EE + e);
    if ((unsigned)dst >= NN || (unsigned)src >= NN) return;   // safety
    int pos = atomicAdd(&g_wr[dst], 1);
    if ((unsigned)pos < EE) g_col[pos] = src;
}

__global__ void degdis_kernel() {
    int i = blockIdx.x * blockDim.x + threadIdx.x;
    if (i >= NN) return;
    int c = g_cnt[i];
    g_dis[i] = (c > 0) ? rsqrtf((float)c) : 0.f;
}

// ---------------- GEMM: C[N,128] = A1 @ W1^T (+ A2 @ W2^T) (+bias) (*dis) (+GAT epilogue) ----------------
#define BM 64
#define BK 32
// SA1: -1 -> use param A1p (harness input x); else buffer id. SA2/DST: buffer ids.
template <int SA1, int SA2, int DST, bool DUAL, bool BIAS, bool DIS, bool GATE>
__global__ void __launch_bounds__(256)
gemm_k(const float* __restrict__ A1p, const float* __restrict__ W1,
       const float* __restrict__ W2, const float* __restrict__ bias,
       const float* __restrict__ as_, const float* __restrict__ ad_) {
    __shared__ float As[BM * BK];
    __shared__ float Bs[BK * 128];
    const int tid = threadIdx.x;
    const int warp = tid >> 5;
    const int lane = tid & 31;
    const int row0 = blockIdx.x * BM;

    const float* A1 = (SA1 < 0) ? A1p : buf<(SA1 < 0) ? 0 : SA1>();
    const float* A2 = DUAL ? buf<SA2>() : nullptr;
    float* C = buf<DST>();

    float4 acc[8];
#pragma unroll
    for (int i = 0; i < 8; i++) acc[i] = make_float4(0.f, 0.f, 0.f, 0.f);

    const int npass = DUAL ? 2 : 1;
    for (int pass = 0; pass < npass; pass++) {
        const float* A = (pass == 0) ? A1 : A2;
        const float* W = (pass == 0) ? W1 : W2;
        for (int kb = 0; kb < HH; kb += BK) {
            // A tile: As[r*BK + k]
#pragma unroll
            for (int t = 0; t < 2; t++) {
                int idx = tid + t * 256;        // 0..511
                int r = idx >> 3;
                int kk = (idx & 7) * 4;
                float4 v = make_float4(0.f, 0.f, 0.f, 0.f);
                int gr = row0 + r;
                if (gr < NN) v = *(const float4*)&A[gr * HH + kb + kk];
                *(float4*)&As[r * BK + kk] = v;
            }
            // W tile transposed: Bs[k*128 + j] = W[j*128 + kb + k]
#pragma unroll
            for (int t = 0; t < 4; t++) {
                int idx = tid + t * 256;        // 0..1023
                int j = idx >> 3;
                int kk = (idx & 7) * 4;
                float4 v = *(const float4*)&W[j * HH + kb + kk];
                Bs[(kk + 0) * 128 + j] = v.x;
                Bs[(kk + 1) * 128 + j] = v.y;
                Bs[(kk + 2) * 128 + j] = v.z;
                Bs[(kk + 3) * 128 + j] = v.w;
            }
            __syncthreads();
#pragma unroll
            for (int k = 0; k < BK; k++) {
                float4 b = *(const float4*)&Bs[k * 128 + lane * 4];
#pragma unroll
                for (int i = 0; i < 8; i++) {
                    float a = As[(warp * 8 + i) * BK + k];
                    acc[i].x += a * b.x;
                    acc[i].y += a * b.y;
                    acc[i].z += a * b.z;
                    acc[i].w += a * b.w;
                }
            }
            __syncthreads();
        }
    }

    float4 bb = make_float4(0.f, 0.f, 0.f, 0.f);
    if (BIAS) bb = *(const float4*)&bias[lane * 4];
    float4 as4 = make_float4(0.f, 0.f, 0.f, 0.f), ad4 = as4;
    if (GATE) {
        as4 = *(const float4*)&as_[lane * 4];
        ad4 = *(const float4*)&ad_[lane * 4];
    }
#pragma unroll
    for (int i = 0; i < 8; i++) {
        int r = row0 + warp * 8 + i;
        if (r >= NN) continue;            // warp-uniform
        float4 v = acc[i];
        if (BIAS) { v.x += bb.x; v.y += bb.y; v.z += bb.z; v.w += bb.w; }
        if (DIS) {
            float d = g_dis[r];
            v.x *= d; v.y *= d; v.z *= d; v.w *= d;
        }
        *(float4*)&C[r * HH + lane * 4] = v;
        if (GATE) {
            float ps = v.x * as4.x + v.y * as4.y + v.z * as4.z + v.w * as4.w;
            float pd = v.x * ad4.x + v.y * ad4.y + v.z * ad4.z + v.w * ad4.w;
#pragma unroll
            for (int off = 16; off; off >>= 1) {
                ps += __shfl_xor_sync(0xffffffff, ps, off);
                pd += __shfl_xor_sync(0xffffffff, pd, off);
            }
            if (lane == 0) { g_ls[r] = ps; g_ld[r] = pd; }
        }
    }
}

// ---------------- edge aggregation: one warp per node (CSR gather) ----------------
template <int CUR>
__global__ void __launch_bounds__(256)
agg_kernel(const float* __restrict__ eps_ptr) {
    const float* cur = buf<CUR>();
    int n = (blockIdx.x * blockDim.x + threadIdx.x) >> 5;
    int lane = threadIdx.x & 31;
    if (n >= NN) return;
    int start = g_rowptr[n];
    int end = g_rowptr[n + 1];
    float ldn = g_ld[n];

    // pass 1: segment max of GAT logits (lane-parallel over edges)
    float m = -INFINITY;
    for (int i = start + lane; i < end; i += 32) {
        int s = g_col[i];
        float l = g_ls[s] + ldn;
        l = (l >= 0.f) ? l : 0.2f * l;
        m = fmaxf(m, l);
    }
#pragma unroll
    for (int off = 16; off; off >>= 1) m = fmaxf(m, __shfl_xor_sync(0xffffffff, m, off));

    // pass 2: vector gathers, warp-wide (each lane owns 4 contiguous columns)
    float4 aX = make_float4(0.f, 0.f, 0.f, 0.f);
    float4 aG = aX, aA = aX;
    float z = 0.f;
    for (int i = start; i < end; i++) {
        int s = g_col[i];
        float l = g_ls[s] + ldn;
        l = (l >= 0.f) ? l : 0.2f * l;
        float e = expf(l - m);
        z += e;
        float4 x4 = *(const float4*)&cur[s * HH + lane * 4];
        aX.x += x4.x; aX.y += x4.y; aX.z += x4.z; aX.w += x4.w;
        float4 g4 = *(const float4*)&g_hgcn[s * HH + lane * 4];
        aG.x += g4.x; aG.y += g4.y; aG.z += g4.z; aG.w += g4.w;
        float4 a4 = *(const float4*)&g_hgat[s * HH + lane * 4];
        aA.x += e * a4.x; aA.y += e * a4.y; aA.z += e * a4.z; aA.w += e * a4.w;
    }

    float degn = (float)(end - start);
    float inv = 1.f / fmaxf(degn, 1.f);
    float eps1 = 1.f + *eps_ptr;
    float disn = g_dis[n];
    float zinv = 1.f / (z + 1e-16f);
    float4 c4 = *(const float4*)&cur[n * HH + lane * 4];

    float4 o;
    o.x = aX.x * inv; o.y = aX.y * inv; o.z = aX.z * inv; o.w = aX.w * inv;
    *(float4*)&g_aggn[n * HH + lane * 4] = o;
    o.x = eps1 * c4.x + aX.x; o.y = eps1 * c4.y + aX.y;
    o.z = eps1 * c4.z + aX.z; o.w = eps1 * c4.w + aX.w;
    *(float4*)&g_ginin[n * HH + lane * 4] = o;
    o.x = disn * aG.x; o.y = disn * aG.y; o.z = disn * aG.z; o.w = disn * aG.w;
    *(float4*)&g_gcnout[n * HH + lane * 4] = o;
    o.x = zinv * aA.x; o.y = zinv * aA.y; o.z = zinv * aA.z; o.w = zinv * aA.w;
    *(float4*)&g_gatout[n * HH + lane * 4] = o;
}

// ---------------- combine: next = sum_i w_i * elu(op_i) ----------------
template <int DST>
__global__ void combine_kernel(int l) {
    int idx = blockIdx.x * blockDim.x + threadIdx.x;
    if (idx >= NN * HH / 4) return;
    float* outb = buf<DST>();
    float w0 = g_naw[l * 4 + 0], w1 = g_naw[l * 4 + 1];
    float w2 = g_naw[l * 4 + 2], w3 = g_naw[l * 4 + 3];
    float4 a = ((const float4*)g_gcnout)[idx];
    float4 b = ((const float4*)g_sage)[idx];
    float4 c = ((const float4*)g_gin)[idx];
    float4 d = ((const float4*)g_gatout)[idx];
    float4 o;
    o.x = w0 * eluf(a.x) + w1 * eluf(b.x) + w2 * eluf(c.x) + w3 * eluf(d.x);
    o.y = w0 * eluf(a.y) + w1 * eluf(b.y) + w2 * eluf(c.y) + w3 * eluf(d.y);
    o.z = w0 * eluf(a.z) + w1 * eluf(b.z) + w2 * eluf(c.z) + w3 * eluf(d.z);
    o.w = w0 * eluf(a.w) + w1 * eluf(b.w) + w2 * eluf(c.w) + w3 * eluf(d.w);
    ((float4*)outb)[idx] = o;
}

// ---------------- skip connections + layer aggregator ----------------
__global__ void x5_kernel() {
    int idx = blockIdx.x * blockDim.x + threadIdx.x;
    if (idx >= NN * HH / 4) return;
    float sc0 = g_scw[1], sc1 = g_scw[3];
    float la0 = g_law[0], la1 = g_law[1], la2 = g_law[2];
    float4 a = ((const float4*)g_x3)[idx];
    float4 b = ((const float4*)g_x1)[idx];
    float4 c = ((const float4*)g_x2)[idx];
    b.x *= sc0; b.y *= sc0; b.z *= sc0; b.w *= sc0;
    c.x *= sc1; c.y *= sc1; c.z *= sc1; c.w *= sc1;
    float4 o;
#define ONE(f)                                                          \
    {                                                                   \
        float mx = fmaxf(fmaxf(a.f, b.f), c.f);                         \
        float sm = a.f + b.f + c.f;                                     \
        float mn = sm * (1.f / 3.f);                                    \
        o.f = la0 * fmaxf(mx, 0.f) + la1 * fmaxf(mn, 0.f) + la2 * fmaxf(sm, 0.f); \
    }
    ONE(x) ONE(y) ONE(z) ONE(w)
#undef ONE
    ((float4*)g_x5)[idx] = o;
}

// ---------------- node classifier: out[N,40] = x5 @ ncW^T + b ----------------
__global__ void __launch_bounds__(256)
nc_kernel(const float* __restrict__ Wnc, const float* __restrict__ bnc,
          float* __restrict__ out) {
    __shared__ float Ws[NC * 132];
    __shared__ float bs[NC];
    int tid = threadIdx.x;
    for (int i = tid; i < NC * HH; i += 256) {
        int j = i / HH, k = i % HH;
        Ws[j * 132 + k] = Wnc[i];
    }
    if (tid < NC) bs[tid] = bnc[tid];
    __syncthreads();
    int row = blockIdx.x * 64 + (tid >> 2);
    int c0 = (tid & 3) * 10;
    if (row >= NN) return;
    float acc[10];
#pragma unroll
    for (int j = 0; j < 10; j++) acc[j] = 0.f;
    const float* xr = &g_x5[row * HH];
    for (int k = 0; k < HH; k++) {
        float a = xr[k];
#pragma unroll
        for (int j = 0; j < 10; j++) acc[j] += a * Ws[(c0 + j) * 132 + k];
    }
#pragma unroll
    for (int j = 0; j < 10; j++) out[row * NC + c0 + j] = acc[j] + bs[c0 + j];
}

// ---------------- host ----------------
static const int TPB = 256;
static const int GB = (NN + BM - 1) / BM;

template <int CUR, int DST>
static void run_layer(int l, const float* gcn_W, const float* gcn_b,
                      const float* sage_Ws, const float* sage_Wn,
                      const float* gin_W, const float* gin_b, const float* gin_eps,
                      const float* gat_W, const float* gat_as, const float* gat_ad) {
    // GCN: (cur @ W^T + b) * dis[row]   -> g_hgcn (id 4)
    gemm_k<CUR, 0, 4, false, true, true, false><<<GB, 256>>>(
        nullptr, gcn_W + l * HH * HH, nullptr, gcn_b + l * HH, nullptr, nullptr);
    // GAT: h = cur @ W^T -> g_hgat (id 5); epilogue writes g_ls/g_ld
    gemm_k<CUR, 0, 5, false, false, false, true><<<GB, 256>>>(
        nullptr, gat_W + l * HH * HH, nullptr, nullptr, gat_as + l * HH, gat_ad + l * HH);
    // edge aggregation
    agg_kernel<CUR><<<(NN * 32 + TPB - 1) / TPB, TPB>>>(gin_eps + l);
    // SAGE: cur @ Ws^T + aggn @ Wn^T -> g_sage (id 10)
    gemm_k<CUR, 6, 10, true, false, false, false><<<GB, 256>>>(
        nullptr, sage_Ws + l * HH * HH, sage_Wn + l * HH * HH, nullptr, nullptr, nullptr);
    // GIN: ginin @ W^T + b -> g_gin (id 11)
    gemm_k<7, 0, 11, false, true, false, false><<<GB, 256>>>(
        nullptr, gin_W + l * HH * HH, nullptr, gin_b + l * HH, nullptr, nullptr);
    // next = sum w_i * elu(op_i)
    combine_kernel<DST><<<(NN * HH / 4 + TPB - 1) / TPB, TPB>>>(l);
}

extern "C" void kernel_launch(void* const* d_in, const int* in_sizes, int n_in,
                              void* d_out, int out_size) {
    const float* x       = (const float*)d_in[0];
    const void*  ei      = d_in[1];
    const float* na_a    = (const float*)d_in[2];
    const float* sc_a    = (const float*)d_in[3];
    const float* la_a    = (const float*)d_in[4];
    const float* lin1_W  = (const float*)d_in[5];
    const float* lin1_b  = (const float*)d_in[6];
    const float* gcn_W   = (const float*)d_in[7];
    const float* gcn_b   = (const float*)d_in[8];
    const float* sage_Ws = (const float*)d_in[9];
    const float* sage_Wn = (const float*)d_in[10];
    const float* gin_W   = (const float*)d_in[11];
    const float* gin_b   = (const float*)d_in[12];
    const float* gin_eps = (const float*)d_in[13];
    const float* gat_W   = (const float*)d_in[14];
    const float* gat_as  = (const float*)d_in[15];
    const float* gat_ad  = (const float*)d_in[16];
    const float* nc_W    = (const float*)d_in[17];
    const float* nc_b    = (const float*)d_in[18];
    float*       out     = (float*)d_out;

    // edge dtype detection + CSR build
    detect_kernel<<<1, 512>>>((const int*)ei);
    zero_cnt_kernel<<<(NN + TPB - 1) / TPB, TPB>>>();
    count_kernel<<<(EE + TPB - 1) / TPB, TPB>>>(ei);
    scan_kernel<<<1, 1024>>>();
    fill_kernel<<<(EE + TPB - 1) / TPB, TPB>>>(ei);
    degdis_kernel<<<(NN + TPB - 1) / TPB, TPB>>>();
    softmax_small_kernel<<<1, 32>>>(na_a, sc_a, la_a);

    // h0 = x @ lin1_W^T + b  -> g_h0 (id 0)
    gemm_k<-1, 0, 0, false, true, false, false><<<GB, 256>>>(
        x, lin1_W, nullptr, lin1_b, nullptr, nullptr);

    run_layer<0, 1>(0, gcn_W, gcn_b, sage_Ws, sage_Wn, gin_W, gin_b, gin_eps,
                    gat_W, gat_as, gat_ad);
    run_layer<1, 2>(1, gcn_W, gcn_b, sage_Ws, sage_Wn, gin_W, gin_b, gin_eps,
                    gat_W, gat_as, gat_ad);
    run_layer<2, 3>(2, gcn_W, gcn_b, sage_Ws, sage_Wn, gin_W, gin_b, gin_eps,
                    gat_W, gat_as, gat_ad);

    x5_kernel<<<(NN * HH / 4 + TPB - 1) / TPB, TPB>>>();
    nc_kernel<<<(NN + 63) / 64, 256>>>(nc_W, nc_b, out);
}

// round 7
// speedup vs baseline: 1.5415x; 1.5415x over previous
#include <cuda_runtime.h>
#include <cuda_bf16.h>
#include <math.h>
#include <stdint.h>

#define NN 50000
#define EE 800000
#define HH 128
#define NC 40
#define AST 72   // padded smem row stride (bf16) -> 144B, conflict-free ldmatrix

// ==================== scratch ====================
__device__ int   g_is64;
__device__ int   g_cnt[NN];
__device__ int   g_rowptr[NN + 1];
__device__ int   g_wr[NN];
__device__ int   g_col[EE];
__device__ float g_dis[NN];
__device__ float g_sn[NN];
__device__ float g_ls[NN], g_ld[NN];
__device__ float g_vs[3 * HH], g_vd[3 * HH];
__device__ float g_h0[NN * HH];
__device__ float g_x1[NN * HH], g_x2[NN * HH], g_x3[NN * HH];
__device__ float g_gcnin[NN * HH], g_gatin[NN * HH];
__device__ float g_aggn[NN * HH], g_ginin[NN * HH];
__device__ float g_gcnout[NN * HH], g_gatout[NN * HH];
__device__ float g_sage[NN * HH], g_gin[NN * HH];
__device__ float g_x5[NN * HH];
__device__ float g_naw[12], g_scw[4], g_law[3];
// bf16 hi/lo weights, plain row-major [n][k] per matrix.
// idx: 0=lin1, 1..3=gcn, 4..6=sage_Ws, 7..9=sage_Wn, 10..12=gin, 13..15=gat
__device__ __nv_bfloat16 g_wh[16 * 16384];
__device__ __nv_bfloat16 g_wl[16 * 16384];

template <int ID>
__device__ __forceinline__ float* buf() {
    if (ID == 0)  return g_h0;
    if (ID == 1)  return g_x1;
    if (ID == 2)  return g_x2;
    if (ID == 3)  return g_x3;
    if (ID == 4)  return g_gcnin;
    if (ID == 5)  return g_gatin;
    if (ID == 6)  return g_aggn;
    if (ID == 7)  return g_ginin;
    if (ID == 8)  return g_gcnout;
    if (ID == 9)  return g_gatout;
    if (ID == 10) return g_sage;
    if (ID == 11) return g_gin;
    return g_x5;
}

__device__ __forceinline__ float eluf(float x) { return x > 0.f ? x : expm1f(x); }
__device__ __forceinline__ int edge_at(const void* p, int idx) {
    if (g_is64) return (int)((const long long*)p)[idx];
    return ((const int*)p)[idx];
}
__device__ __forceinline__ uint32_t smem_u32(const void* p) {
    uint32_t a;
    asm("{ .reg .u64 t; cvta.to.shared.u64 t, %1; cvt.u32.u64 %0, t; }" : "=r"(a) : "l"(p));
    return a;
}
__device__ __forceinline__ unsigned pack2bf(__nv_bfloat16 a, __nv_bfloat16 b) {
    return (unsigned)__bfloat16_as_ushort(a) | ((unsigned)__bfloat16_as_ushort(b) << 16);
}

// ==================== edge dtype detection ====================
__global__ void detect_kernel(const int* __restrict__ p) {
    __shared__ int nz;
    if (threadIdx.x == 0) nz = 0;
    __syncthreads();
    int local = 0;
    for (int i = threadIdx.x * 2 + 1; i < 8192; i += 2 * blockDim.x)
        if (p[i] != 0) local = 1;
    if (local) atomicOr(&nz, 1);
    __syncthreads();
    if (threadIdx.x == 0) g_is64 = nz ? 0 : 1;
}

// ==================== tiny softmaxes ====================
__global__ void softmax_small_kernel(const float* __restrict__ na,
                                     const float* __restrict__ sc,
                                     const float* __restrict__ la) {
    if (threadIdx.x != 0 || blockIdx.x != 0) return;
    for (int r = 0; r < 3; r++) {
        float m = -1e30f;
        for (int j = 0; j < 4; j++) m = fmaxf(m, na[r * 4 + j]);
        float z = 0.f, e[4];
        for (int j = 0; j < 4; j++) { e[j] = expf(na[r * 4 + j] - m); z += e[j]; }
        for (int j = 0; j < 4; j++) g_naw[r * 4 + j] = e[j] / z;
    }
    for (int r = 0; r < 2; r++) {
        float m = fmaxf(sc[r * 2], sc[r * 2 + 1]);
        float e0 = expf(sc[r * 2] - m), e1 = expf(sc[r * 2 + 1] - m);
        g_scw[r * 2] = e0 / (e0 + e1);
        g_scw[r * 2 + 1] = e1 / (e0 + e1);
    }
    {
        float m = fmaxf(fmaxf(la[0], la[1]), la[2]);
        float e0 = expf(la[0] - m), e1 = expf(la[1] - m), e2 = expf(la[2] - m);
        float z = e0 + e1 + e2;
        g_law[0] = e0 / z; g_law[1] = e1 / z; g_law[2] = e2 / z;
    }
}

// ==================== CSR build ====================
__global__ void zero_cnt_kernel() {
    int i = blockIdx.x * blockDim.x + threadIdx.x;
    if (i < NN) g_cnt[i] = 0;
}
__global__ void count_kernel(const void* __restrict__ ei) {
    int e = blockIdx.x * blockDim.x + threadIdx.x;
    if (e >= EE) return;
    int dst = edge_at(ei, EE + e);
    if ((unsigned)dst >= NN) return;
    atomicAdd(&g_cnt[dst], 1);
}
__global__ void scan2_kernel() {
    const int PER = 49;
    int tid = threadIdx.x;
    int base = tid * PER;
    int s = 0;
    for (int i = 0; i < PER; i++) {
        int idx = base + i;
        if (idx < NN) s += g_cnt[idx];
    }
    int lane = tid & 31, wid = tid >> 5;
    int incl = s;
#pragma unroll
    for (int off = 1; off < 32; off <<= 1) {
        int t = __shfl_up_sync(0xffffffffu, incl, off);
        if (lane >= off) incl += t;
    }
    __shared__ int wsum[32];
    __shared__ int total;
    if (lane == 31) wsum[wid] = incl;
    __syncthreads();
    if (wid == 0) {
        int v = wsum[lane];
        int wi = v;
#pragma unroll
        for (int off = 1; off < 32; off <<= 1) {
            int t = __shfl_up_sync(0xffffffffu, wi, off);
            if (lane >= off) wi += t;
        }
        wsum[lane] = wi - v;
        if (lane == 31) total = wi;
    }
    __syncthreads();
    int run = wsum[wid] + incl - s;
    for (int i = 0; i < PER; i++) {
        int idx = base + i;
        if (idx < NN) { g_rowptr[idx] = run; g_wr[idx] = run; run += g_cnt[idx]; }
    }
    if (tid == 0) g_rowptr[NN] = total;
}
__global__ void fill_kernel(const void* __restrict__ ei) {
    int e = blockIdx.x * blockDim.x + threadIdx.x;
    if (e >= EE) return;
    int src = edge_at(ei, e);
    int dst = edge_at(ei, EE + e);
    if ((unsigned)dst >= NN || (unsigned)src >= NN) return;
    int pos = atomicAdd(&g_wr[dst], 1);
    if ((unsigned)pos < EE) g_col[pos] = src;
}
__global__ void degdis_kernel() {
    int i = blockIdx.x * blockDim.x + threadIdx.x;
    if (i >= NN) return;
    int c = g_cnt[i];
    g_dis[i] = (c > 0) ? rsqrtf((float)c) : 0.f;
}

// ==================== weight conversion (fp32 -> bf16 hi/lo, row-major) ====================
struct WP { const float* p[16]; };
__global__ void convert_w_kernel(WP wp) {
    int mat = blockIdx.y;
    int i = blockIdx.x * 256 + threadIdx.x;   // 0..16383 = n*128+k
    float v = wp.p[mat][i];
    __nv_bfloat16 h = __float2bfloat16(v);
    __nv_bfloat16 l = __float2bfloat16(v - __bfloat162float(h));
    g_wh[mat * 16384 + i] = h;
    g_wl[mat * 16384 + i] = l;
}

// ==================== GAT projection vectors: v = W^T a ====================
__global__ void gatvec_kernel(const float* __restrict__ gat_W,
                              const float* __restrict__ gat_as,
                              const float* __restrict__ gat_ad) {
    int l = blockIdx.y, which = blockIdx.x, k = threadIdx.x;
    const float* W = gat_W + l * HH * HH;
    const float* a = (which ? gat_ad : gat_as) + l * HH;
    float acc = 0.f;
    for (int n = 0; n < HH; n++) acc += W[n * HH + k] * a[n];
    (which ? g_vd : g_vs)[l * HH + k] = acc;
}

// ==================== per-node GAT logits ====================
template <int CUR>
__global__ void __launch_bounds__(256) lsld_kernel(int l) {
    __shared__ float svs[HH], svd[HH];
    int tid = threadIdx.x;
    if (tid < HH) { svs[tid] = g_vs[l * HH + tid]; svd[tid] = g_vd[l * HH + tid]; }
    __syncthreads();
    int n = blockIdx.x * 8 + (tid >> 5);
    int lane = tid & 31;
    if (n >= NN) return;
    const float* cur = buf<CUR>();
    float4 c = *(const float4*)&cur[(size_t)n * HH + lane * 4];
    float4 a = *(const float4*)&svs[lane * 4];
    float4 b = *(const float4*)&svd[lane * 4];
    float ps = c.x * a.x + c.y * a.y + c.z * a.z + c.w * a.w;
    float pd = c.x * b.x + c.y * b.y + c.z * b.z + c.w * b.w;
#pragma unroll
    for (int off = 16; off; off >>= 1) {
        ps += __shfl_xor_sync(0xffffffffu, ps, off);
        pd += __shfl_xor_sync(0xffffffffu, pd, off);
    }
    if (lane == 0) { g_ls[n] = ps; g_ld[n] = pd; }
}

// ==================== edge aggregation: gather ONLY cur[src] ====================
template <int CUR>
__global__ void __launch_bounds__(256) agg2_kernel(const float* __restrict__ eps_ptr) {
    const float* cur = buf<CUR>();
    int n = (blockIdx.x * blockDim.x + threadIdx.x) >> 5;
    int lane = threadIdx.x & 31;
    if (n >= NN) return;
    int start = g_rowptr[n], end = g_rowptr[n + 1];
    float ldn = g_ld[n];

    float m = -INFINITY, sd = 0.f;
    for (int i = start + lane; i < end; i += 32) {
        int s = g_col[i];
        float l = g_ls[s] + ldn;
        l = (l >= 0.f) ? l : 0.2f * l;
        m = fmaxf(m, l);
        sd += g_dis[s];
    }
#pragma unroll
    for (int off = 16; off; off >>= 1) {
        m = fmaxf(m, __shfl_xor_sync(0xffffffffu, m, off));
        sd += __shfl_xor_sync(0xffffffffu, sd, off);
    }

    float4 S1 = make_float4(0, 0, 0, 0), Sd = S1, Sa = S1;
    float z = 0.f;
    for (int i = start; i < end; i++) {
        int s = g_col[i];
        float l = g_ls[s] + ldn;
        l = (l >= 0.f) ? l : 0.2f * l;
        float e = expf(l - m);
        z += e;
        float ds = g_dis[s];
        float4 x4 = *(const float4*)&cur[(size_t)s * HH + lane * 4];
        S1.x += x4.x; S1.y += x4.y; S1.z += x4.z; S1.w += x4.w;
        Sd.x += ds * x4.x; Sd.y += ds * x4.y; Sd.z += ds * x4.z; Sd.w += ds * x4.w;
        Sa.x += e * x4.x; Sa.y += e * x4.y; Sa.z += e * x4.z; Sa.w += e * x4.w;
    }

    float deg = (float)(end - start);
    float inv = 1.f / fmaxf(deg, 1.f);
    float eps1 = 1.f + *eps_ptr;
    float disn = g_dis[n];
    float zinv = 1.f / (z + 1e-16f);
    float4 c4 = *(const float4*)&cur[(size_t)n * HH + lane * 4];
    size_t o = (size_t)n * HH + lane * 4;

    float4 t;
    t.x = S1.x * inv; t.y = S1.y * inv; t.z = S1.z * inv; t.w = S1.w * inv;
    *(float4*)&g_aggn[o] = t;
    t.x = eps1 * c4.x + S1.x; t.y = eps1 * c4.y + S1.y;
    t.z = eps1 * c4.z + S1.z; t.w = eps1 * c4.w + S1.w;
    *(float4*)&g_ginin[o] = t;
    t.x = disn * Sd.x; t.y = disn * Sd.y; t.z = disn * Sd.z; t.w = disn * Sd.w;
    *(float4*)&g_gcnin[o] = t;
    t.x = zinv * Sa.x; t.y = zinv * Sa.y; t.z = zinv * Sa.z; t.w = zinv * Sa.w;
    *(float4*)&g_gatin[o] = t;
    if (lane == 0) g_sn[n] = disn * sd;
}

// ==================== mma.sync GEMM: C[128x128] = A @ W^T, bf16 3-term hi/lo ====================
// BMODE: 0=none, 1=+bias, 2=+sn*bias
template <int SA1, int WI1, int SA2, int WI2, int DST, int BMODE>
__global__ void __launch_bounds__(256, 2)
gemm_mma(const float* __restrict__ A1p, const float* __restrict__ bias) {
    __shared__ __nv_bfloat16 sA[128 * AST];
    __shared__ __nv_bfloat16 sB[128 * AST];
    __shared__ float sbias[128];
    const int tid = threadIdx.x, lane = tid & 31, warp = tid >> 5;
    const int wm = warp >> 1, wn = warp & 1;     // 4x2 warp grid
    const int row0 = blockIdx.x * 128;
    if (BMODE && tid < 128) sbias[tid] = bias[tid];
    const uint32_t sAu = smem_u32(sA), sBu = smem_u32(sB);

    float acc[2][8][4];
#pragma unroll
    for (int a = 0; a < 2; a++)
#pragma unroll
        for (int b = 0; b < 8; b++)
#pragma unroll
            for (int c = 0; c < 4; c++) acc[a][b][c] = 0.f;

    const int npass = (SA2 >= 0) ? 2 : 1;
    for (int pass = 0; pass < npass; pass++) {
        const float* A = (pass == 0)
            ? ((SA1 < 0) ? A1p : buf<(SA1 < 0) ? 0 : SA1>())
            : buf<(SA2 < 0) ? 0 : SA2>();
        const int wi = (pass == 0) ? WI1 : ((WI2 < 0) ? 0 : WI2);
        const __nv_bfloat16* WH = g_wh + wi * 16384;
        const __nv_bfloat16* WL = g_wl + wi * 16384;

        for (int ab = 0; ab < 4; ab++) {              // A tiles: hi-k0, hi-k64, lo-k0, lo-k64
            const int av = ab >> 1, kh = (ab & 1) << 6;
            __syncthreads();
            // stage A tile (fp32 -> bf16 variant av)
            {
                const float4* Ag = (const float4*)A;
#pragma unroll
                for (int it = 0; it < 8; it++) {
                    int idx = tid + it * 256;             // 0..2047
                    int r = idx >> 4, c = (idx & 15) << 2;
                    int gr = row0 + r;
                    float4 v = (gr < NN) ? Ag[(size_t)gr * 32 + (kh >> 2) + (c >> 2)]
                                         : make_float4(0, 0, 0, 0);
                    __nv_bfloat16 hx = __float2bfloat16(v.x), hy = __float2bfloat16(v.y);
                    __nv_bfloat16 hz = __float2bfloat16(v.z), hw = __float2bfloat16(v.w);
                    unsigned p0, p1;
                    if (av == 0) {
                        p0 = pack2bf(hx, hy); p1 = pack2bf(hz, hw);
                    } else {
                        p0 = pack2bf(__float2bfloat16(v.x - __bfloat162float(hx)),
                                     __float2bfloat16(v.y - __bfloat162float(hy)));
                        p1 = pack2bf(__float2bfloat16(v.z - __bfloat162float(hz)),
                                     __float2bfloat16(v.w - __bfloat162float(hw)));
                    }
                    uint2* d = (uint2*)&sA[r * AST + c];
                    *d = make_uint2(p0, p1);
                }
            }
            const int nW = (av == 0) ? 2 : 1;             // hi: Whi,Wlo ; lo: Whi
            for (int wv = 0; wv < nW; wv++) {
                const __nv_bfloat16* Wsrc = (av == 0) ? (wv == 0 ? WH : WL) : WH;
                __syncthreads();
                // stage W tile (bf16, k-half kh)
                {
                    const uint4* Wg = (const uint4*)Wsrc;
#pragma unroll
                    for (int it = 0; it < 4; it++) {
                        int idx = tid + it * 256;        // 0..1023
                        int nrow = idx >> 3, c = (idx & 7) << 3;
                        uint4 v = Wg[nrow * 16 + (kh >> 3) + (c >> 3)];
                        *(uint4*)&sB[nrow * AST + c] = v;
                    }
                }
                __syncthreads();
#pragma unroll
                for (int ks = 0; ks < 4; ks++) {
                    int k0 = ks * 16;
                    uint32_t af[2][4];
#pragma unroll
                    for (int mi = 0; mi < 2; mi++) {
                        int grp = lane >> 3, rr = lane & 7;
                        int row = wm * 32 + mi * 16 + ((grp & 1) << 3) + rr;
                        int col = k0 + ((grp >> 1) << 3);
                        uint32_t ad = sAu + (row * AST + col) * 2;
                        asm volatile(
                            "ldmatrix.sync.aligned.m8n8.x4.shared.b16 {%0,%1,%2,%3}, [%4];"
                            : "=r"(af[mi][0]), "=r"(af[mi][1]), "=r"(af[mi][2]), "=r"(af[mi][3])
                            : "r"(ad));
                    }
                    uint32_t bf[4][4];
#pragma unroll
                    for (int p = 0; p < 4; p++) {
                        int grp = lane >> 3, rr = lane & 7;
                        int row = wn * 64 + p * 16 + ((grp >> 1) << 3) + rr;
                        int col = k0 + ((grp & 1) << 3);
                        uint32_t ad = sBu + (row * AST + col) * 2;
                        asm volatile(
                            "ldmatrix.sync.aligned.m8n8.x4.shared.b16 {%0,%1,%2,%3}, [%4];"
                            : "=r"(bf[p][0]), "=r"(bf[p][1]), "=r"(bf[p][2]), "=r"(bf[p][3])
                            : "r"(ad));
                    }
#pragma unroll
                    for (int mi = 0; mi < 2; mi++)
#pragma unroll
                        for (int ni = 0; ni < 8; ni++) {
                            uint32_t b0 = bf[ni >> 1][(ni & 1) * 2];
                            uint32_t b1 = bf[ni >> 1][(ni & 1) * 2 + 1];
                            asm volatile(
                                "mma.sync.aligned.m16n8k16.row.col.f32.bf16.bf16.f32 "
                                "{%0,%1,%2,%3}, {%4,%5,%6,%7}, {%8,%9}, {%0,%1,%2,%3};"
                                : "+f"(acc[mi][ni][0]), "+f"(acc[mi][ni][1]),
                                  "+f"(acc[mi][ni][2]), "+f"(acc[mi][ni][3])
                                : "r"(af[mi][0]), "r"(af[mi][1]), "r"(af[mi][2]), "r"(af[mi][3]),
                                  "r"(b0), "r"(b1));
                        }
                }
            }
        }
    }
    __syncthreads();

    // epilogue
    float* C = buf<DST>();
#pragma unroll
    for (int mi = 0; mi < 2; mi++) {
        int rA = row0 + wm * 32 + mi * 16 + (lane >> 2);
        int rB = rA + 8;
        float snA = 0.f, snB = 0.f;
        if (BMODE == 2) {
            snA = (rA < NN) ? g_sn[rA] : 0.f;
            snB = (rB < NN) ? g_sn[rB] : 0.f;
        }
#pragma unroll
        for (int ni = 0; ni < 8; ni++) {
            int col = wn * 64 + ni * 8 + (lane & 3) * 2;
            float2 vA = make_float2(acc[mi][ni][0], acc[mi][ni][1]);
            float2 vB = make_float2(acc[mi][ni][2], acc[mi][ni][3]);
            if (BMODE == 1) {
                vA.x += sbias[col]; vA.y += sbias[col + 1];
                vB.x += sbias[col]; vB.y += sbias[col + 1];
            }
            if (BMODE == 2) {
                vA.x += snA * sbias[col]; vA.y += snA * sbias[col + 1];
                vB.x += snB * sbias[col]; vB.y += snB * sbias[col + 1];
            }
            if (rA < NN) *(float2*)&C[(size_t)rA * HH + col] = vA;
            if (rB < NN) *(float2*)&C[(size_t)rB * HH + col] = vB;
        }
    }
}

// ==================== combine ====================
template <int DST>
__global__ void combine_kernel(int l) {
    int idx = blockIdx.x * blockDim.x + threadIdx.x;
    if (idx >= NN * HH / 4) return;
    float* outb = buf<DST>();
    float w0 = g_naw[l * 4 + 0], w1 = g_naw[l * 4 + 1];
    float w2 = g_naw[l * 4 + 2], w3 = g_naw[l * 4 + 3];
    float4 a = ((const float4*)g_gcnout)[idx];
    float4 b = ((const float4*)g_sage)[idx];
    float4 c = ((const float4*)g_gin)[idx];
    float4 d = ((const float4*)g_gatout)[idx];
    float4 o;
    o.x = w0 * eluf(a.x) + w1 * eluf(b.x) + w2 * eluf(c.x) + w3 * eluf(d.x);
    o.y = w0 * eluf(a.y) + w1 * eluf(b.y) + w2 * eluf(c.y) + w3 * eluf(d.y);
    o.z = w0 * eluf(a.z) + w1 * eluf(b.z) + w2 * eluf(c.z) + w3 * eluf(d.z);
    o.w = w0 * eluf(a.w) + w1 * eluf(b.w) + w2 * eluf(c.w) + w3 * eluf(d.w);
    ((float4*)outb)[idx] = o;
}

// ==================== skip + layer aggregator ====================
__global__ void x5_kernel() {
    int idx = blockIdx.x * blockDim.x + threadIdx.x;
    if (idx >= NN * HH / 4) return;
    float sc0 = g_scw[1], sc1 = g_scw[3];
    float la0 = g_law[0], la1 = g_law[1], la2 = g_law[2];
    float4 a = ((const float4*)g_x3)[idx];
    float4 b = ((const float4*)g_x1)[idx];
    float4 c = ((const float4*)g_x2)[idx];
    b.x *= sc0; b.y *= sc0; b.z *= sc0; b.w *= sc0;
    c.x *= sc1; c.y *= sc1; c.z *= sc1; c.w *= sc1;
    float4 o;
#define ONE(f)                                                          \
    {                                                                   \
        float mx = fmaxf(fmaxf(a.f, b.f), c.f);                         \
        float sm = a.f + b.f + c.f;                                     \
        float mn = sm * (1.f / 3.f);                                    \
        o.f = la0 * fmaxf(mx, 0.f) + la1 * fmaxf(mn, 0.f) + la2 * fmaxf(sm, 0.f); \
    }
    ONE(x) ONE(y) ONE(z) ONE(w)
#undef ONE
    ((float4*)g_x5)[idx] = o;
}

// ==================== node classifier ====================
__global__ void __launch_bounds__(256)
nc_kernel(const float* __restrict__ Wnc, const float* __restrict__ bnc,
          float* __restrict__ out) {
    __shared__ float Ws[NC * 132];
    __shared__ float bs[NC];
    int tid = threadIdx.x;
    for (int i = tid; i < NC * HH; i += 256) {
        int j = i / HH, k = i % HH;
        Ws[j * 132 + k] = Wnc[i];
    }
    if (tid < NC) bs[tid] = bnc[tid];
    __syncthreads();
    int row = blockIdx.x * 64 + (tid >> 2);
    int c0 = (tid & 3) * 10;
    if (row >= NN) return;
    float acc[10];
#pragma unroll
    for (int j = 0; j < 10; j++) acc[j] = 0.f;
    const float* xr = &g_x5[(size_t)row * HH];
    for (int k = 0; k < HH; k++) {
        float a = xr[k];
#pragma unroll
        for (int j = 0; j < 10; j++) acc[j] += a * Ws[(c0 + j) * 132 + k];
    }
#pragma unroll
    for (int j = 0; j < 10; j++) out[row * NC + c0 + j] = acc[j] + bs[c0 + j];
}

// ==================== host ====================
static const int TPB = 256;
static const int GGB = (NN + 127) / 128;   // 391

#define LAUNCH_GEMM(SA1, WI1, SA2, WI2, DST, BM_, Aptr, Bptr) \
    gemm_mma<SA1, WI1, SA2, WI2, DST, BM_><<<GGB, 256>>>(Aptr, Bptr)

template <int CUR, int DST, int L>
static void run_layer(const float* gcn_b, const float* gin_b, const float* gin_eps) {
    lsld_kernel<CUR><<<(NN + 7) / 8, 256>>>(L);
    agg2_kernel<CUR><<<(NN * 32 + TPB - 1) / TPB, TPB>>>(gin_eps + L);
    LAUNCH_GEMM(4, 1 + L, -1, -1, 8, 2, nullptr, gcn_b + L * HH);      // GCN
    LAUNCH_GEMM(5, 13 + L, -1, -1, 9, 0, nullptr, nullptr);            // GAT
    LAUNCH_GEMM(CUR, 4 + L, 6, 7 + L, 10, 0, nullptr, nullptr);        // SAGE (dual)
    LAUNCH_GEMM(7, 10 + L, -1, -1, 11, 1, nullptr, gin_b + L * HH);    // GIN
    combine_kernel<DST><<<(NN * HH / 4 + TPB - 1) / TPB, TPB>>>(L);
}

extern "C" void kernel_launch(void* const* d_in, const int* in_sizes, int n_in,
                              void* d_out, int out_size) {
    const float* x       = (const float*)d_in[0];
    const void*  ei      = d_in[1];
    const float* na_a    = (const float*)d_in[2];
    const float* sc_a    = (const float*)d_in[3];
    const float* la_a    = (const float*)d_in[4];
    const float* lin1_W  = (const float*)d_in[5];
    const float* lin1_b  = (const float*)d_in[6];
    const float* gcn_W   = (const float*)d_in[7];
    const float* gcn_b   = (const float*)d_in[8];
    const float* sage_Ws = (const float*)d_in[9];
    const float* sage_Wn = (const float*)d_in[10];
    const float* gin_W   = (const float*)d_in[11];
    const float* gin_b   = (const float*)d_in[12];
    const float* gin_eps = (const float*)d_in[13];
    const float* gat_W   = (const float*)d_in[14];
    const float* gat_as  = (const float*)d_in[15];
    const float* gat_ad  = (const float*)d_in[16];
    const float* nc_W    = (const float*)d_in[17];
    const float* nc_b    = (const float*)d_in[18];
    float*       out     = (float*)d_out;

    detect_kernel<<<1, 512>>>((const int*)ei);
    zero_cnt_kernel<<<(NN + TPB - 1) / TPB, TPB>>>();
    count_kernel<<<(EE + TPB - 1) / TPB, TPB>>>(ei);
    scan2_kernel<<<1, 1024>>>();
    fill_kernel<<<(EE + TPB - 1) / TPB, TPB>>>(ei);
    degdis_kernel<<<(NN + TPB - 1) / TPB, TPB>>>();
    softmax_small_kernel<<<1, 32>>>(na_a, sc_a, la_a);

    WP wp;
    wp.p[0] = lin1_W;
    for (int l = 0; l < 3; l++) {
        wp.p[1 + l]  = gcn_W + l * HH * HH;
        wp.p[4 + l]  = sage_Ws + l * HH * HH;
        wp.p[7 + l]  = sage_Wn + l * HH * HH;
        wp.p[10 + l] = gin_W + l * HH * HH;
        wp.p[13 + l] = gat_W + l * HH * HH;
    }
    convert_w_kernel<<<dim3(64, 16), 256>>>(wp);
    gatvec_kernel<<<dim3(2, 3), 128>>>(gat_W, gat_as, gat_ad);

    // h0 = x @ lin1_W^T + b
    LAUNCH_GEMM(-1, 0, -1, -1, 0, 1, x, lin1_b);

    run_layer<0, 1, 0>(gcn_b, gin_b, gin_eps);
    run_layer<1, 2, 1>(gcn_b, gin_b, gin_eps);
    run_layer<2, 3, 2>(gcn_b, gin_b, gin_eps);

    x5_kernel<<<(NN * HH / 4 + TPB - 1) / TPB, TPB>>>();
    nc_kernel<<<(NN + 63) / 64, 256>>>(nc_W, nc_b, out);
}

// round 9
// speedup vs baseline: 1.7007x; 1.1032x over previous
#include <cuda_runtime.h>
#include <cuda_bf16.h>
#include <math.h>
#include <stdint.h>

#define NN 50000
#define EE 800000
#define HH 128
#define NC 40

// ==================== scratch ====================
__device__ int   g_is64;
__device__ int   g_cnt[NN];
__device__ int   g_part[256];
__device__ int   g_rowptr[NN + 1];
__device__ int   g_wr[NN];
__device__ int   g_col[EE];
__device__ float g_dis[NN];
__device__ float g_sn[NN];
__device__ float g_ls[NN], g_ld[NN];
__device__ float g_vs[3 * HH], g_vd[3 * HH];
__device__ float g_h0[NN * HH];
__device__ float g_x1[NN * HH], g_x2[NN * HH], g_x3[NN * HH];
__device__ float g_gcnin[NN * HH], g_gatin[NN * HH];
__device__ float g_aggn[NN * HH], g_ginin[NN * HH];
__device__ float g_x5[NN * HH];
__device__ float g_naw[12], g_scw[4], g_law[3];
// bf16 hi/lo weights, row-major [n][k].
// idx: 0=lin1, 1..3=gcn, 4..6=sage_Ws, 7..9=sage_Wn, 10..12=gin, 13..15=gat
__device__ __nv_bfloat16 g_wh[16 * 16384];
__device__ __nv_bfloat16 g_wl[16 * 16384];

template <int ID>
__device__ __forceinline__ float* buf() {
    if (ID == 0)  return g_h0;
    if (ID == 1)  return g_x1;
    if (ID == 2)  return g_x2;
    if (ID == 3)  return g_x3;
    if (ID == 4)  return g_gcnin;
    if (ID == 5)  return g_gatin;
    if (ID == 6)  return g_aggn;
    if (ID == 7)  return g_ginin;
    return g_x5;
}

__device__ __forceinline__ float eluf(float x) { return x > 0.f ? x : expm1f(x); }
__device__ __forceinline__ int edge_at(const void* p, int idx) {
    if (g_is64) return (int)((const long long*)p)[idx];
    return ((const int*)p)[idx];
}
__device__ __forceinline__ uint32_t smem_u32(const void* p) {
    uint32_t a;
    asm("{ .reg .u64 t; cvta.to.shared.u64 t, %1; cvt.u32.u64 %0, t; }" : "=r"(a) : "l"(p));
    return a;
}
__device__ __forceinline__ unsigned pack2bf(__nv_bfloat16 a, __nv_bfloat16 b) {
    return (unsigned)__bfloat16_as_ushort(a) | ((unsigned)__bfloat16_as_ushort(b) << 16);
}

// ==================== edge dtype detection ====================
__global__ void detect_kernel(const int* __restrict__ p) {
    __shared__ int nz;
    if (threadIdx.x == 0) nz = 0;
    __syncthreads();
    int local = 0;
    for (int i = threadIdx.x * 2 + 1; i < 8192; i += 2 * blockDim.x)
        if (p[i] != 0) local = 1;
    if (local) atomicOr(&nz, 1);
    __syncthreads();
    if (threadIdx.x == 0) g_is64 = nz ? 0 : 1;
}

// ==================== tiny softmaxes ====================
__global__ void softmax_small_kernel(const float* __restrict__ na,
                                     const float* __restrict__ sc,
                                     const float* __restrict__ la) {
    if (threadIdx.x != 0 || blockIdx.x != 0) return;
    for (int r = 0; r < 3; r++) {
        float m = -1e30f;
        for (int j = 0; j < 4; j++) m = fmaxf(m, na[r * 4 + j]);
        float z = 0.f, e[4];
        for (int j = 0; j < 4; j++) { e[j] = expf(na[r * 4 + j] - m); z += e[j]; }
        for (int j = 0; j < 4; j++) g_naw[r * 4 + j] = e[j] / z;
    }
    for (int r = 0; r < 2; r++) {
        float m = fmaxf(sc[r * 2], sc[r * 2 + 1]);
        float e0 = expf(sc[r * 2] - m), e1 = expf(sc[r * 2 + 1] - m);
        g_scw[r * 2] = e0 / (e0 + e1);
        g_scw[r * 2 + 1] = e1 / (e0 + e1);
    }
    {
        float m = fmaxf(fmaxf(la[0], la[1]), la[2]);
        float e0 = expf(la[0] - m), e1 = expf(la[1] - m), e2 = expf(la[2] - m);
        float z = e0 + e1 + e2;
        g_law[0] = e0 / z; g_law[1] = e1 / z; g_law[2] = e2 / z;
    }
}

// ==================== CSR build ====================
__global__ void zero_cnt_kernel() {
    int i = blockIdx.x * blockDim.x + threadIdx.x;
    if (i < NN) g_cnt[i] = 0;
}
__global__ void count_kernel(const void* __restrict__ ei) {
    int e = blockIdx.x * blockDim.x + threadIdx.x;
    if (e >= EE) return;
    int dst = edge_at(ei, EE + e);
    if ((unsigned)dst >= NN) return;
    atomicAdd(&g_cnt[dst], 1);
}
// 3-phase coalesced scan over g_cnt -> g_rowptr/g_wr
__global__ void scan_part() {          // grid 196, block 256
    int tid = threadIdx.x, lane = tid & 31, wid = tid >> 5;
    int idx = blockIdx.x * 256 + tid;
    int v = (idx < NN) ? g_cnt[idx] : 0;
#pragma unroll
    for (int off = 16; off; off >>= 1) v += __shfl_xor_sync(0xffffffffu, v, off);
    __shared__ int ws[8];
    if (lane == 0) ws[wid] = v;
    __syncthreads();
    if (tid == 0) {
        int s = 0;
#pragma unroll
        for (int i = 0; i < 8; i++) s += ws[i];
        g_part[blockIdx.x] = s;
    }
}
__global__ void scan_mid() {           // 1 block, 256
    int tid = threadIdx.x, lane = tid & 31, wid = tid >> 5;
    int v = (tid < 196) ? g_part[tid] : 0;
    int incl = v;
#pragma unroll
    for (int off = 1; off < 32; off <<= 1) {
        int t = __shfl_up_sync(0xffffffffu, incl, off);
        if (lane >= off) incl += t;
    }
    __shared__ int ws[8];
    __shared__ int tot;
    if (lane == 31) ws[wid] = incl;
    __syncthreads();
    if (wid == 0) {
        int u = (lane < 8) ? ws[lane] : 0, ui = u;
#pragma unroll
        for (int off = 1; off < 8; off <<= 1) {
            int t = __shfl_up_sync(0xffffffffu, ui, off);
            if (lane >= off) ui += t;
        }
        if (lane < 8) ws[lane] = ui - u;
        if (lane == 7) tot = ui;
    }
    __syncthreads();
    int excl = ws[wid] + incl - v;
    if (tid < 196) g_part[tid] = excl;
    if (tid == 0) g_rowptr[NN] = tot;
}
__global__ void scan_fin() {           // grid 196, block 256
    int tid = threadIdx.x, lane = tid & 31, wid = tid >> 5;
    int idx = blockIdx.x * 256 + tid;
    int v = (idx < NN) ? g_cnt[idx] : 0;
    int incl = v;
#pragma unroll
    for (int off = 1; off < 32; off <<= 1) {
        int t = __shfl_up_sync(0xffffffffu, incl, off);
        if (lane >= off) incl += t;
    }
    __shared__ int ws[8];
    if (lane == 31) ws[wid] = incl;
    __syncthreads();
    if (wid == 0) {
        int u = (lane < 8) ? ws[lane] : 0, ui = u;
#pragma unroll
        for (int off = 1; off < 8; off <<= 1) {
            int t = __shfl_up_sync(0xffffffffu, ui, off);
            if (lane >= off) ui += t;
        }
        if (lane < 8) ws[lane] = ui - u;
    }
    __syncthreads();
    int excl = g_part[blockIdx.x] + ws[wid] + incl - v;
    if (idx < NN) { g_rowptr[idx] = excl; g_wr[idx] = excl; }
}
__global__ void fill_kernel(const void* __restrict__ ei) {
    int e = blockIdx.x * blockDim.x + threadIdx.x;
    if (e >= EE) return;
    int src = edge_at(ei, e);
    int dst = edge_at(ei, EE + e);
    if ((unsigned)dst >= NN || (unsigned)src >= NN) return;
    int pos = atomicAdd(&g_wr[dst], 1);
    if ((unsigned)pos < EE) g_col[pos] = src;
}
__global__ void degdis_kernel() {
    int i = blockIdx.x * blockDim.x + threadIdx.x;
    if (i >= NN) return;
    int c = g_cnt[i];
    g_dis[i] = (c > 0) ? rsqrtf((float)c) : 0.f;
}
__global__ void zero_lsld_kernel() {
    int i = blockIdx.x * blockDim.x + threadIdx.x;
    if (i < NN) { g_ls[i] = 0.f; g_ld[i] = 0.f; }
}

// ==================== weight conversion ====================
struct WP { const float* p[16]; };
__global__ void convert_w_kernel(WP wp) {
    int mat = blockIdx.y;
    int i = blockIdx.x * 256 + threadIdx.x;   // n*128+k
    float v = wp.p[mat][i];
    __nv_bfloat16 h = __float2bfloat16(v);
    __nv_bfloat16 l = __float2bfloat16(v - __bfloat162float(h));
    g_wh[mat * 16384 + i] = h;
    g_wl[mat * 16384 + i] = l;
}

// ==================== GAT projection vectors: v = W^T a ====================
__global__ void gatvec_kernel(const float* __restrict__ gat_W,
                              const float* __restrict__ gat_as,
                              const float* __restrict__ gat_ad) {
    int l = blockIdx.y, which = blockIdx.x, k = threadIdx.x;
    const float* W = gat_W + l * HH * HH;
    const float* a = (which ? gat_ad : gat_as) + l * HH;
    float acc = 0.f;
    for (int n = 0; n < HH; n++) acc += W[n * HH + k] * a[n];
    (which ? g_vd : g_vs)[l * HH + k] = acc;
}

// ==================== edge aggregation ====================
template <int CUR>
__global__ void __launch_bounds__(256) agg2_kernel(const float* __restrict__ eps_ptr) {
    const float* cur = buf<CUR>();
    int n = (blockIdx.x * blockDim.x + threadIdx.x) >> 5;
    int lane = threadIdx.x & 31;
    if (n >= NN) return;
    int start = g_rowptr[n], end = g_rowptr[n + 1];
    float ldn = g_ld[n];

    float m = -INFINITY, sd = 0.f;
    for (int i = start + lane; i < end; i += 32) {
        int s = g_col[i];
        float l = g_ls[s] + ldn;
        l = (l >= 0.f) ? l : 0.2f * l;
        m = fmaxf(m, l);
        sd += g_dis[s];
    }
#pragma unroll
    for (int off = 16; off; off >>= 1) {
        m = fmaxf(m, __shfl_xor_sync(0xffffffffu, m, off));
        sd += __shfl_xor_sync(0xffffffffu, sd, off);
    }

    float4 S1 = make_float4(0, 0, 0, 0), Sd = S1, Sa = S1;
    float z = 0.f;
    for (int i = start; i < end; i++) {
        int s = g_col[i];
        float l = g_ls[s] + ldn;
        l = (l >= 0.f) ? l : 0.2f * l;
        float e = expf(l - m);
        z += e;
        float ds = g_dis[s];
        float4 x4 = *(const float4*)&cur[(size_t)s * HH + lane * 4];
        S1.x += x4.x; S1.y += x4.y; S1.z += x4.z; S1.w += x4.w;
        Sd.x += ds * x4.x; Sd.y += ds * x4.y; Sd.z += ds * x4.z; Sd.w += ds * x4.w;
        Sa.x += e * x4.x; Sa.y += e * x4.y; Sa.z += e * x4.z; Sa.w += e * x4.w;
    }

    float deg = (float)(end - start);
    float inv = 1.f / fmaxf(deg, 1.f);
    float eps1 = 1.f + *eps_ptr;
    float disn = g_dis[n];
    float zinv = 1.f / (z + 1e-16f);
    float4 c4 = *(const float4*)&cur[(size_t)n * HH + lane * 4];
    size_t o = (size_t)n * HH + lane * 4;

    float4 t;
    t.x = S1.x * inv; t.y = S1.y * inv; t.z = S1.z * inv; t.w = S1.w * inv;
    *(float4*)&g_aggn[o] = t;
    t.x = eps1 * c4.x + S1.x; t.y = eps1 * c4.y + S1.y;
    t.z = eps1 * c4.z + S1.z; t.w = eps1 * c4.w + S1.w;
    *(float4*)&g_ginin[o] = t;
    t.x = disn * Sd.x; t.y = disn * Sd.y; t.z = disn * Sd.z; t.w = disn * Sd.w;
    *(float4*)&g_gcnin[o] = t;
    t.x = zinv * Sa.x; t.y = zinv * Sa.y; t.z = zinv * Sa.z; t.w = zinv * Sa.w;
    *(float4*)&g_gatin[o] = t;
    if (lane == 0) g_sn[n] = disn * sd;
}

// ==================== mma.sync GEMM with fused combine/lsld epilogue ====================
// BMODE: 0=none, 1=+bias, 2=+sn*bias
// CMODE: 0=plain write, 1=write w*elu(v), 2=RMW += w*elu(v)
// LSLDV: -1 none, else vector set index; OP: naw op index
#define SMEM_GEMM 88576

template <int SA1, int WI1, int SA2, int WI2, int DST, int BMODE, int CMODE, int LSLDV, int OP>
__global__ void __launch_bounds__(256, 2)
gemm_mma(const float* __restrict__ A1p, const float* __restrict__ bias, int l) {
    extern __shared__ char smem[];
    __nv_bfloat16* sAhi = (__nv_bfloat16*)smem;              // 128 x 136
    __nv_bfloat16* sAlo = sAhi + 128 * 136;                  // 128 x 136
    __nv_bfloat16* sW   = sAlo + 128 * 136;                  // 128 x 72
    float* sbias = (float*)(sW + 128 * 72);                  // 128
    const int tid = threadIdx.x, lane = tid & 31, warp = tid >> 5;
    const int wm = warp >> 1, wn = warp & 1;
    const int row0 = blockIdx.x * 128;
    if (BMODE && tid < 128) sbias[tid] = bias[tid];
    const uint32_t sAhiU = smem_u32(sAhi), sAloU = smem_u32(sAlo), sWU = smem_u32(sW);

    float acc[2][8][4];
#pragma unroll
    for (int a = 0; a < 2; a++)
#pragma unroll
        for (int b = 0; b < 8; b++)
#pragma unroll
            for (int c = 0; c < 4; c++) acc[a][b][c] = 0.f;

    const int npass = (SA2 >= 0) ? 2 : 1;
    for (int pass = 0; pass < npass; pass++) {
        const float* A = (pass == 0)
            ? ((SA1 < 0) ? A1p : buf<(SA1 < 0) ? 0 : SA1>())
            : buf<(SA2 < 0) ? 0 : SA2>();
        const int wi = (pass == 0) ? WI1 : ((WI2 < 0) ? 0 : WI2);
        const __nv_bfloat16* WHp = g_wh + wi * 16384;
        const __nv_bfloat16* WLp = g_wl + wi * 16384;

        __syncthreads();
        // stage A once: fp32 -> hi + lo tiles
        {
            const float4* Ag = (const float4*)A;
#pragma unroll
            for (int it = 0; it < 16; it++) {
                int idx = tid + it * 256;          // 0..4095
                int r = idx >> 5, c4 = idx & 31;
                int gr = row0 + r;
                float4 v = (gr < NN) ? Ag[(size_t)gr * 32 + c4] : make_float4(0, 0, 0, 0);
                __nv_bfloat16 hx = __float2bfloat16(v.x), hy = __float2bfloat16(v.y);
                __nv_bfloat16 hz = __float2bfloat16(v.z), hw = __float2bfloat16(v.w);
                unsigned h0 = pack2bf(hx, hy), h1 = pack2bf(hz, hw);
                unsigned l0 = pack2bf(__float2bfloat16(v.x - __bfloat162float(hx)),
                                      __float2bfloat16(v.y - __bfloat162float(hy)));
                unsigned l1 = pack2bf(__float2bfloat16(v.z - __bfloat162float(hz)),
                                      __float2bfloat16(v.w - __bfloat162float(hw)));
                *(uint2*)&sAhi[r * 136 + c4 * 4] = make_uint2(h0, h1);
                *(uint2*)&sAlo[r * 136 + c4 * 4] = make_uint2(l0, l1);
            }
        }
        for (int kh = 0; kh < 2; kh++) {
            for (int wv = 0; wv < 2; wv++) {
                const __nv_bfloat16* Wsrc = wv ? WLp : WHp;
                __syncthreads();       // first iter: also covers A staging
                // stage W half (128 rows x 64 cols) = 1024 uint4 chunks
#pragma unroll
                for (int it = 0; it < 4; it++) {
                    int idx = tid + it * 256;      // 0..1023
                    int rrow = idx >> 3, c8 = (idx & 7) * 8;
                    *(uint4*)&sW[rrow * 72 + c8] =
                        *(const uint4*)&Wsrc[rrow * 128 + kh * 64 + c8];
                }
                __syncthreads();
#pragma unroll
                for (int ks = 0; ks < 4; ks++) {
                    int k0 = ks * 16;
                    uint32_t bfr[4][4];
#pragma unroll
                    for (int p = 0; p < 4; p++) {
                        int grp = lane >> 3, rr = lane & 7;
                        int row = wn * 64 + p * 16 + ((grp >> 1) << 3) + rr;
                        int col = k0 + ((grp & 1) << 3);
                        uint32_t ad = sWU + (row * 72 + col) * 2;
                        asm volatile(
                            "ldmatrix.sync.aligned.m8n8.x4.shared.b16 {%0,%1,%2,%3}, [%4];"
                            : "=r"(bfr[p][0]), "=r"(bfr[p][1]), "=r"(bfr[p][2]), "=r"(bfr[p][3])
                            : "r"(ad));
                    }
                    uint32_t ah[2][4];
#pragma unroll
                    for (int mi = 0; mi < 2; mi++) {
                        int grp = lane >> 3, rr = lane & 7;
                        int row = wm * 32 + mi * 16 + ((grp & 1) << 3) + rr;
                        int col = kh * 64 + k0 + ((grp >> 1) << 3);
                        uint32_t ad = sAhiU + (row * 136 + col) * 2;
                        asm volatile(
                            "ldmatrix.sync.aligned.m8n8.x4.shared.b16 {%0,%1,%2,%3}, [%4];"
                            : "=r"(ah[mi][0]), "=r"(ah[mi][1]), "=r"(ah[mi][2]), "=r"(ah[mi][3])
                            : "r"(ad));
                    }
#pragma unroll
                    for (int mi = 0; mi < 2; mi++)
#pragma unroll
                        for (int ni = 0; ni < 8; ni++) {
                            uint32_t b0 = bfr[ni >> 1][(ni & 1) * 2];
                            uint32_t b1 = bfr[ni >> 1][(ni & 1) * 2 + 1];
                            asm volatile(
                                "mma.sync.aligned.m16n8k16.row.col.f32.bf16.bf16.f32 "
                                "{%0,%1,%2,%3}, {%4,%5,%6,%7}, {%8,%9}, {%0,%1,%2,%3};"
                                : "+f"(acc[mi][ni][0]), "+f"(acc[mi][ni][1]),
                                  "+f"(acc[mi][ni][2]), "+f"(acc[mi][ni][3])
                                : "r"(ah[mi][0]), "r"(ah[mi][1]), "r"(ah[mi][2]), "r"(ah[mi][3]),
                                  "r"(b0), "r"(b1));
                        }
                    if (wv == 0) {
                        uint32_t al[2][4];
#pragma unroll
                        for (int mi = 0; mi < 2; mi++) {
                            int grp = lane >> 3, rr = lane & 7;
                            int row = wm * 32 + mi * 16 + ((grp & 1) << 3) + rr;
                            int col = kh * 64 + k0 + ((grp >> 1) << 3);
                            uint32_t ad = sAloU + (row * 136 + col) * 2;
                            asm volatile(
                                "ldmatrix.sync.aligned.m8n8.x4.shared.b16 {%0,%1,%2,%3}, [%4];"
                                : "=r"(al[mi][0]), "=r"(al[mi][1]), "=r"(al[mi][2]), "=r"(al[mi][3])
                                : "r"(ad));
                        }
#pragma unroll
                        for (int mi = 0; mi < 2; mi++)
#pragma unroll
                            for (int ni = 0; ni < 8; ni++) {
                                uint32_t b0 = bfr[ni >> 1][(ni & 1) * 2];
                                uint32_t b1 = bfr[ni >> 1][(ni & 1) * 2 + 1];
                                asm volatile(
                                    "mma.sync.aligned.m16n8k16.row.col.f32.bf16.bf16.f32 "
                                    "{%0,%1,%2,%3}, {%4,%5,%6,%7}, {%8,%9}, {%0,%1,%2,%3};"
                                    : "+f"(acc[mi][ni][0]), "+f"(acc[mi][ni][1]),
                                      "+f"(acc[mi][ni][2]), "+f"(acc[mi][ni][3])
                                    : "r"(al[mi][0]), "r"(al[mi][1]), "r"(al[mi][2]), "r"(al[mi][3]),
                                      "r"(b0), "r"(b1));
                            }
                    }
                }
            }
        }
    }
    __syncthreads();

    // ---------- epilogue ----------
    const float w = (CMODE >= 1) ? g_naw[l * 4 + OP] : 0.f;
    const int lv = (LSLDV >= 0) ? LSLDV : 0;
    const float* vsv = g_vs + lv * HH;
    const float* vdv = g_vd + lv * HH;
    float* C = buf<DST>();
#pragma unroll
    for (int mi = 0; mi < 2; mi++) {
        int rA = row0 + wm * 32 + mi * 16 + (lane >> 2);
        int rB = rA + 8;
        float snA = 0.f, snB = 0.f;
        if (BMODE == 2) {
            snA = (rA < NN) ? g_sn[rA] : 0.f;
            snB = (rB < NN) ? g_sn[rB] : 0.f;
        }
        float psA = 0.f, pdA = 0.f, psB = 0.f, pdB = 0.f;
#pragma unroll
        for (int ni = 0; ni < 8; ni++) {
            int col = wn * 64 + ni * 8 + (lane & 3) * 2;
            float2 vA = make_float2(acc[mi][ni][0], acc[mi][ni][1]);
            float2 vB = make_float2(acc[mi][ni][2], acc[mi][ni][3]);
            if (BMODE == 1) {
                vA.x += sbias[col]; vA.y += sbias[col + 1];
                vB.x += sbias[col]; vB.y += sbias[col + 1];
            }
            if (BMODE == 2) {
                vA.x += snA * sbias[col]; vA.y += snA * sbias[col + 1];
                vB.x += snB * sbias[col]; vB.y += snB * sbias[col + 1];
            }
            if (CMODE >= 1) {
                vA.x = w * eluf(vA.x); vA.y = w * eluf(vA.y);
                vB.x = w * eluf(vB.x); vB.y = w * eluf(vB.y);
            }
            if (rA < NN) {
                float2* cp = (float2*)&C[(size_t)rA * HH + col];
                if (CMODE == 2) { float2 o = *cp; vA.x += o.x; vA.y += o.y; }
                *cp = vA;
            }
            if (rB < NN) {
                float2* cp = (float2*)&C[(size_t)rB * HH + col];
                if (CMODE == 2) { float2 o = *cp; vB.x += o.x; vB.y += o.y; }
                *cp = vB;
            }
            if (LSLDV >= 0) {
                float s0 = __ldg(&vsv[col]), s1 = __ldg(&vsv[col + 1]);
                float d0 = __ldg(&vdv[col]), d1 = __ldg(&vdv[col + 1]);
                psA += vA.x * s0 + vA.y * s1; pdA += vA.x * d0 + vA.y * d1;
                psB += vB.x * s0 + vB.y * s1; pdB += vB.x * d0 + vB.y * d1;
            }
        }
        if (LSLDV >= 0) {
            psA += __shfl_xor_sync(0xffffffffu, psA, 1);
            psA += __shfl_xor_sync(0xffffffffu, psA, 2);
            pdA += __shfl_xor_sync(0xffffffffu, pdA, 1);
            pdA += __shfl_xor_sync(0xffffffffu, pdA, 2);
            psB += __shfl_xor_sync(0xffffffffu, psB, 1);
            psB += __shfl_xor_sync(0xffffffffu, psB, 2);
            pdB += __shfl_xor_sync(0xffffffffu, pdB, 1);
            pdB += __shfl_xor_sync(0xffffffffu, pdB, 2);
            if ((lane & 3) == 0) {
                if (rA < NN) { atomicAdd(&g_ls[rA], psA); atomicAdd(&g_ld[rA], pdA); }
                if (rB < NN) { atomicAdd(&g_ls[rB], psB); atomicAdd(&g_ld[rB], pdB); }
            }
        }
    }
}

// ==================== skip + layer aggregator ====================
__global__ void x5_kernel() {
    int idx = blockIdx.x * blockDim.x + threadIdx.x;
    if (idx >= NN * HH / 4) return;
    float sc0 = g_scw[1], sc1 = g_scw[3];
    float la0 = g_law[0], la1 = g_law[1], la2 = g_law[2];
    float4 a = ((const float4*)g_x3)[idx];
    float4 b = ((const float4*)g_x1)[idx];
    float4 c = ((const float4*)g_x2)[idx];
    b.x *= sc0; b.y *= sc0; b.z *= sc0; b.w *= sc0;
    c.x *= sc1; c.y *= sc1; c.z *= sc1; c.w *= sc1;
    float4 o;
#define ONE(f)                                                          \
    {                                                                   \
        float mx = fmaxf(fmaxf(a.f, b.f), c.f);                         \
        float sm = a.f + b.f + c.f;                                     \
        float mn = sm * (1.f / 3.f);                                    \
        o.f = la0 * fmaxf(mx, 0.f) + la1 * fmaxf(mn, 0.f) + la2 * fmaxf(sm, 0.f); \
    }
    ONE(x) ONE(y) ONE(z) ONE(w)
#undef ONE
    ((float4*)g_x5)[idx] = o;
}

// ==================== node classifier ====================
__global__ void __launch_bounds__(256)
nc_kernel(const float* __restrict__ Wnc, const float* __restrict__ bnc,
          float* __restrict__ out) {
    __shared__ float Ws[NC * 132];
    __shared__ float bs[NC];
    int tid = threadIdx.x;
    for (int i = tid; i < NC * HH; i += 256) {
        int j = i / HH, k = i % HH;
        Ws[j * 132 + k] = Wnc[i];
    }
    if (tid < NC) bs[tid] = bnc[tid];
    __syncthreads();
    int row = blockIdx.x * 64 + (tid >> 2);
    int c0 = (tid & 3) * 10;
    if (row >= NN) return;
    float acc[10];
#pragma unroll
    for (int j = 0; j < 10; j++) acc[j] = 0.f;
    const float* xr = &g_x5[(size_t)row * HH];
    for (int k = 0; k < HH; k++) {
        float a = xr[k];
#pragma unroll
        for (int j = 0; j < 10; j++) acc[j] += a * Ws[(c0 + j) * 132 + k];
    }
#pragma unroll
    for (int j = 0; j < 10; j++) out[row * NC + c0 + j] = acc[j] + bs[c0 + j];
}

// ==================== host ====================
static const int TPB = 256;
static const int GGB = (NN + 127) / 128;   // 391
static const int SB  = (NN + 255) / 256;   // 196

#define LAUNCH_GEMM(SA1, WI1, SA2, WI2, DST, BM_, CM_, LV_, OP_, Aptr, Bptr, lArg)    \
    do {                                                                              \
        cudaFuncSetAttribute(gemm_mma<SA1, WI1, SA2, WI2, DST, BM_, CM_, LV_, OP_>,   \
                             cudaFuncAttributeMaxDynamicSharedMemorySize, SMEM_GEMM); \
        gemm_mma<SA1, WI1, SA2, WI2, DST, BM_, CM_, LV_, OP_>                         \
            <<<GGB, 256, SMEM_GEMM>>>(Aptr, Bptr, lArg);                              \
    } while (0)

template <int CUR, int DST, int L>
static void run_layer(const float* gcn_b, const float* gin_b, const float* gin_eps) {
    agg2_kernel<CUR><<<(NN * 32 + TPB - 1) / TPB, TPB>>>(gin_eps + L);
    // GCN: first combine write
    LAUNCH_GEMM(4, 1 + L, -1, -1, DST, 2, 1, -1, 0, nullptr, gcn_b + L * HH, L);
    // GAT: RMW
    LAUNCH_GEMM(5, 13 + L, -1, -1, DST, 0, 2, -1, 3, nullptr, nullptr, L);
    // SAGE (dual): RMW
    LAUNCH_GEMM(CUR, 4 + L, 6, 7 + L, DST, 0, 2, -1, 1, nullptr, nullptr, L);
    // GIN: RMW, final -> also produces lsld for next layer
    if (L < 2) zero_lsld_kernel<<<SB, 256>>>();
    constexpr int LV = (L < 2) ? (L + 1) : -1;
    LAUNCH_GEMM(7, 10 + L, -1, -1, DST, 1, 2, LV, 2, nullptr, gin_b + L * HH, L);
}

extern "C" void kernel_launch(void* const* d_in, const int* in_sizes, int n_in,
                              void* d_out, int out_size) {
    const float* x       = (const float*)d_in[0];
    const void*  ei      = d_in[1];
    const float* na_a    = (const float*)d_in[2];
    const float* sc_a    = (const float*)d_in[3];
    const float* la_a    = (const float*)d_in[4];
    const float* lin1_W  = (const float*)d_in[5];
    const float* lin1_b  = (const float*)d_in[6];
    const float* gcn_W   = (const float*)d_in[7];
    const float* gcn_b   = (const float*)d_in[8];
    const float* sage_Ws = (const float*)d_in[9];
    const float* sage_Wn = (const float*)d_in[10];
    const float* gin_W   = (const float*)d_in[11];
    const float* gin_b   = (const float*)d_in[12];
    const float* gin_eps = (const float*)d_in[13];
    const float* gat_W   = (const float*)d_in[14];
    const float* gat_as  = (const float*)d_in[15];
    const float* gat_ad  = (const float*)d_in[16];
    const float* nc_W    = (const float*)d_in[17];
    const float* nc_b    = (const float*)d_in[18];
    float*       out     = (float*)d_out;

    detect_kernel<<<1, 512>>>((const int*)ei);
    zero_cnt_kernel<<<SB, 256>>>();
    count_kernel<<<(EE + TPB - 1) / TPB, TPB>>>(ei);
    scan_part<<<SB, 256>>>();
    scan_mid<<<1, 256>>>();
    scan_fin<<<SB, 256>>>();
    fill_kernel<<<(EE + TPB - 1) / TPB, TPB>>>(ei);
    degdis_kernel<<<SB, 256>>>();
    softmax_small_kernel<<<1, 32>>>(na_a, sc_a, la_a);

    WP wp;
    wp.p[0] = lin1_W;
    for (int l = 0; l < 3; l++) {
        wp.p[1 + l]  = gcn_W + l * HH * HH;
        wp.p[4 + l]  = sage_Ws + l * HH * HH;
        wp.p[7 + l]  = sage_Wn + l * HH * HH;
        wp.p[10 + l] = gin_W + l * HH * HH;
        wp.p[13 + l] = gat_W + l * HH * HH;
    }
    convert_w_kernel<<<dim3(64, 16), 256>>>(wp);
    gatvec_kernel<<<dim3(2, 3), 128>>>(gat_W, gat_as, gat_ad);

    // h0 = x @ lin1_W^T + b ; epilogue computes lsld for layer 0
    zero_lsld_kernel<<<SB, 256>>>();
    LAUNCH_GEMM(-1, 0, -1, -1, 0, 1, 0, 0, 0, x, lin1_b, 0);

    run_layer<0, 1, 0>(gcn_b, gin_b, gin_eps);
    run_layer<1, 2, 1>(gcn_b, gin_b, gin_eps);
    run_layer<2, 3, 2>(gcn_b, gin_b, gin_eps);

    x5_kernel<<<(NN * HH / 4 + TPB - 1) / TPB, TPB>>>();
    nc_kernel<<<(NN + 63) / 64, 256>>>(nc_W, nc_b, out);
}